// round 2
// baseline (speedup 1.0000x reference)
#include <cuda_runtime.h>
#include <math.h>

// Problem constants
#define BATCH   4
#define SEQ     2048
#define HEADS   16
#define DKV     64
#define DMODEL  1024
#define INNER   1024          // HEADS * DKV
#define MTOT    (BATCH*SEQ)   // 8192

// Scratch (allocation-free rule: __device__ globals)
__device__ float g_q[MTOT * INNER];
__device__ float g_k[MTOT * INNER];
__device__ float g_v[MTOT * INNER];
__device__ float g_ctx[MTOT * INNER];
__device__ float g_bias[HEADS * 4096];   // bias[h][rel + 2047], rel = k - q

// ---------------------------------------------------------------------------
// Relative-position bias table: bias[h][rel+2047] = rel_emb[bucket(rel)][h]
// Mirrors the reference bucket function (bidirectional, 32 buckets, max_dist 128)
// ---------------------------------------------------------------------------
__global__ void bias_table_kernel(const float* __restrict__ rel_emb,
                                  float* __restrict__ bias) {
    int t = blockIdx.x * blockDim.x + threadIdx.x;
    if (t >= HEADS * 4096) return;
    int h   = t >> 12;
    int idx = t & 4095;
    int rel = idx - 2047;                 // k - q
    int bucket = (rel > 0) ? 16 : 0;
    int ap = abs(rel);
    if (ap < 8) {
        bucket += ap;
    } else {
        // 8 + log(ap/8)/log(16) * 8, truncated, clamped to 15
        float v = logf((float)ap * 0.125f) / 2.7725887222397811f * 8.0f;
        int b = 8 + (int)v;
        bucket += (b < 15) ? b : 15;
    }
    bias[h * 4096 + idx] = rel_emb[bucket * HEADS + h];
}

// ---------------------------------------------------------------------------
// SGEMM: C[M,N] = A[M,K] @ B[K,N], row-major, 128x128 block, 8x8 per thread
// ---------------------------------------------------------------------------
__global__ void __launch_bounds__(256)
sgemm128(const float* __restrict__ A, const float* __restrict__ B,
         float* __restrict__ C, int M, int N, int K) {
    __shared__ float As[8][128];   // transposed: As[k][m]
    __shared__ float Bs[8][128];

    int tid = threadIdx.x;
    int tx  = tid & 15;            // 0..15 -> N subtile
    int ty  = tid >> 4;            // 0..15 -> M subtile
    int bm  = blockIdx.y * 128;
    int bn  = blockIdx.x * 128;

    int arow = tid >> 1;           // 0..127
    int acol = (tid & 1) * 4;      // 0 or 4
    int brow = tid >> 5;           // 0..7
    int bcol = (tid & 31) * 4;     // 0..124

    const float* Ag = A + (size_t)(bm + arow) * K + acol;
    const float* Bg = B + (size_t)brow * N + bn + bcol;

    float acc[8][8];
#pragma unroll
    for (int i = 0; i < 8; i++)
#pragma unroll
        for (int j = 0; j < 8; j++) acc[i][j] = 0.0f;

    for (int k0 = 0; k0 < K; k0 += 8) {
        float4 av = *(const float4*)(Ag + k0);
        float4 bv = *(const float4*)(Bg + (size_t)k0 * N);
        As[acol + 0][arow] = av.x;
        As[acol + 1][arow] = av.y;
        As[acol + 2][arow] = av.z;
        As[acol + 3][arow] = av.w;
        *(float4*)&Bs[brow][bcol] = bv;
        __syncthreads();

#pragma unroll
        for (int kk = 0; kk < 8; kk++) {
            float a[8], b[8];
            *(float4*)&a[0] = *(const float4*)&As[kk][ty * 8];
            *(float4*)&a[4] = *(const float4*)&As[kk][ty * 8 + 4];
            *(float4*)&b[0] = *(const float4*)&Bs[kk][tx * 8];
            *(float4*)&b[4] = *(const float4*)&Bs[kk][tx * 8 + 4];
#pragma unroll
            for (int i = 0; i < 8; i++)
#pragma unroll
                for (int j = 0; j < 8; j++)
                    acc[i][j] += a[i] * b[j];
        }
        __syncthreads();
    }

#pragma unroll
    for (int i = 0; i < 8; i++) {
        float* Cp = C + (size_t)(bm + ty * 8 + i) * N + bn + tx * 8;
        *(float4*)Cp       = make_float4(acc[i][0], acc[i][1], acc[i][2], acc[i][3]);
        *(float4*)(Cp + 4) = make_float4(acc[i][4], acc[i][5], acc[i][6], acc[i][7]);
    }
}

// ---------------------------------------------------------------------------
// Flash attention: one CTA = 64 queries of one (b,h). Iterate 64-key tiles,
// online softmax, bias added from precomputed table. fp32 throughout.
// smem layout (dynamic): Qt[64][64] (d-major), Kt[64][64] (d-major),
//                        Ps[64][64] (i-major), Vs[64][64] (j-major), bs[128]
// ---------------------------------------------------------------------------
__global__ void __launch_bounds__(256)
attn_kernel(const float* __restrict__ Q, const float* __restrict__ K,
            const float* __restrict__ V, const float* __restrict__ bias,
            float* __restrict__ Octx) {
    extern __shared__ float smem[];
    float* Qt = smem;              // [d][i]  4096
    float* Kt = smem + 4096;       // [d][j]  4096
    float* Ps = smem + 8192;       // [i][j]  4096
    float* Vs = smem + 12288;      // [j][n]  4096
    float* bs = smem + 16384;      // [128]

    const int qb = blockIdx.x;     // 0..31
    const int h  = blockIdx.y;     // 0..15
    const int b  = blockIdx.z;     // 0..3

    const int tid = threadIdx.x;
    const int tx  = tid & 15;
    const int ty  = tid >> 4;
    const int tx4 = tx * 4;
    const int ty4 = ty * 4;

    const size_t head_off = (size_t)h * DKV;
    const float* bias_h = bias + h * 4096;

    // --- load Q tile (64 rows x 64 d), transpose into Qt[d][i] ---
    {
        int i  = tid >> 2;               // 0..63
        int d0 = (tid & 3) * 16;         // 0,16,32,48
        const float* src = Q + ((size_t)(b * SEQ + qb * 64 + i)) * INNER + head_off + d0;
#pragma unroll
        for (int c4 = 0; c4 < 4; c4++) {
            float4 val = *(const float4*)(src + c4 * 4);
            Qt[(d0 + c4 * 4 + 0) * 64 + i] = val.x;
            Qt[(d0 + c4 * 4 + 1) * 64 + i] = val.y;
            Qt[(d0 + c4 * 4 + 2) * 64 + i] = val.z;
            Qt[(d0 + c4 * 4 + 3) * 64 + i] = val.w;
        }
    }

    float m[4], l[4], acc[4][4];
#pragma unroll
    for (int r = 0; r < 4; r++) {
        m[r] = -INFINITY;
        l[r] = 0.0f;
#pragma unroll
        for (int c = 0; c < 4; c++) acc[r][c] = 0.0f;
    }

    for (int kb = 0; kb < SEQ / 64; kb++) {
        // --- load K tile (transposed) and V tile (natural) ---
        {
            int j  = tid >> 2;
            int d0 = (tid & 3) * 16;
            const float* ksrc = K + ((size_t)(b * SEQ + kb * 64 + j)) * INNER + head_off + d0;
            const float* vsrc = V + ((size_t)(b * SEQ + kb * 64 + j)) * INNER + head_off + d0;
#pragma unroll
            for (int c4 = 0; c4 < 4; c4++) {
                float4 kv = *(const float4*)(ksrc + c4 * 4);
                Kt[(d0 + c4 * 4 + 0) * 64 + j] = kv.x;
                Kt[(d0 + c4 * 4 + 1) * 64 + j] = kv.y;
                Kt[(d0 + c4 * 4 + 2) * 64 + j] = kv.z;
                Kt[(d0 + c4 * 4 + 3) * 64 + j] = kv.w;
                *(float4*)&Vs[j * 64 + d0 + c4 * 4] = *(const float4*)(vsrc + c4 * 4);
            }
            if (tid < 127) {
                int rel = (kb - qb) * 64 + (tid - 63);
                bs[tid] = bias_h[rel + 2047];
            }
        }
        __syncthreads();

        // --- scores: 4x4 per thread over 64-d reduction ---
        float sc[4][4];
#pragma unroll
        for (int r = 0; r < 4; r++)
#pragma unroll
            for (int c = 0; c < 4; c++) sc[r][c] = 0.0f;

#pragma unroll 8
        for (int d = 0; d < 64; d++) {
            float4 qv = *(const float4*)&Qt[d * 64 + ty4];
            float4 kv = *(const float4*)&Kt[d * 64 + tx4];
            float qa[4] = {qv.x, qv.y, qv.z, qv.w};
            float ka[4] = {kv.x, kv.y, kv.z, kv.w};
#pragma unroll
            for (int r = 0; r < 4; r++)
#pragma unroll
                for (int c = 0; c < 4; c++)
                    sc[r][c] += qa[r] * ka[c];
        }

        // --- add bias, online softmax ---
#pragma unroll
        for (int r = 0; r < 4; r++) {
#pragma unroll
            for (int c = 0; c < 4; c++)
                sc[r][c] += bs[tx4 + c - ty4 - r + 63];

            float rowmax = fmaxf(fmaxf(sc[r][0], sc[r][1]), fmaxf(sc[r][2], sc[r][3]));
#pragma unroll
            for (int off = 8; off >= 1; off >>= 1)
                rowmax = fmaxf(rowmax, __shfl_xor_sync(0xffffffffu, rowmax, off, 16));

            float nm    = fmaxf(m[r], rowmax);
            float scale = __expf(m[r] - nm);
            m[r] = nm;

            float rs = 0.0f;
#pragma unroll
            for (int c = 0; c < 4; c++) {
                float p = __expf(sc[r][c] - nm);
                sc[r][c] = p;
                rs += p;
            }
#pragma unroll
            for (int off = 8; off >= 1; off >>= 1)
                rs += __shfl_xor_sync(0xffffffffu, rs, off, 16);

            l[r] = l[r] * scale + rs;
#pragma unroll
            for (int c = 0; c < 4; c++) acc[r][c] *= scale;

            *(float4*)&Ps[(ty4 + r) * 64 + tx4] =
                make_float4(sc[r][0], sc[r][1], sc[r][2], sc[r][3]);
        }
        __syncthreads();

        // --- PV: acc[i][n] += P[i][j] * V[j][n] ---
#pragma unroll 8
        for (int j = 0; j < 64; j++) {
            float4 vv = *(const float4*)&Vs[j * 64 + tx4];
            float p0 = Ps[(ty4 + 0) * 64 + j];
            float p1 = Ps[(ty4 + 1) * 64 + j];
            float p2 = Ps[(ty4 + 2) * 64 + j];
            float p3 = Ps[(ty4 + 3) * 64 + j];
            acc[0][0] += p0 * vv.x; acc[0][1] += p0 * vv.y; acc[0][2] += p0 * vv.z; acc[0][3] += p0 * vv.w;
            acc[1][0] += p1 * vv.x; acc[1][1] += p1 * vv.y; acc[1][2] += p1 * vv.z; acc[1][3] += p1 * vv.w;
            acc[2][0] += p2 * vv.x; acc[2][1] += p2 * vv.y; acc[2][2] += p2 * vv.z; acc[2][3] += p2 * vv.w;
            acc[3][0] += p3 * vv.x; acc[3][1] += p3 * vv.y; acc[3][2] += p3 * vv.z; acc[3][3] += p3 * vv.w;
        }
        __syncthreads();
    }

    // --- epilogue: normalize by l, write ctx[b][s][h*64+n] ---
#pragma unroll
    for (int r = 0; r < 4; r++) {
        float inv = 1.0f / l[r];
        float* dst = Octx + ((size_t)(b * SEQ + qb * 64 + ty4 + r)) * INNER + head_off + tx4;
        *(float4*)dst = make_float4(acc[r][0] * inv, acc[r][1] * inv,
                                    acc[r][2] * inv, acc[r][3] * inv);
    }
}

// ---------------------------------------------------------------------------
// Launch
// ---------------------------------------------------------------------------
extern "C" void kernel_launch(void* const* d_in, const int* in_sizes, int n_in,
                              void* d_out, int out_size) {
    const float* hs      = (const float*)d_in[0];
    const float* Wq      = (const float*)d_in[1];
    const float* Wk      = (const float*)d_in[2];
    const float* Wv      = (const float*)d_in[3];
    const float* Wo      = (const float*)d_in[4];
    const float* rel_emb = (const float*)d_in[5];
    float* out = (float*)d_out;

    float *pq, *pk, *pv, *pctx, *pbias;
    cudaGetSymbolAddress((void**)&pq,    g_q);
    cudaGetSymbolAddress((void**)&pk,    g_k);
    cudaGetSymbolAddress((void**)&pv,    g_v);
    cudaGetSymbolAddress((void**)&pctx,  g_ctx);
    cudaGetSymbolAddress((void**)&pbias, g_bias);

    // No static guard (harness rule): set attribute unconditionally each call.
    cudaFuncSetAttribute(attn_kernel,
                         cudaFuncAttributeMaxDynamicSharedMemorySize,
                         (16384 + 128) * (int)sizeof(float));

    // bias table
    bias_table_kernel<<<(HEADS * 4096 + 255) / 256, 256>>>(rel_emb, pbias);

    // QKV projections: [8192,1024] @ [1024,1024]
    dim3 ggrid(INNER / 128, MTOT / 128);
    sgemm128<<<ggrid, 256>>>(hs, Wq, pq, MTOT, INNER, DMODEL);
    sgemm128<<<ggrid, 256>>>(hs, Wk, pk, MTOT, INNER, DMODEL);
    sgemm128<<<ggrid, 256>>>(hs, Wv, pv, MTOT, INNER, DMODEL);

    // attention
    dim3 agrid(SEQ / 64, HEADS, BATCH);
    size_t asmem = (16384 + 128) * sizeof(float);
    attn_kernel<<<agrid, 256, asmem>>>(pq, pk, pv, pbias, pctx);

    // output projection
    dim3 ogrid(DMODEL / 128, MTOT / 128);
    sgemm128<<<ogrid, 256>>>(pctx, Wo, out, MTOT, DMODEL, DMODEL);
}